// round 8
// baseline (speedup 1.0000x reference)
#include <cuda_runtime.h>
#include <cuda_bf16.h>
#include <mma.h>
#include <math.h>

using namespace nvcuda;

#define BB    256
#define TS    120
#define PREDN 24
#define NJ    15
#define HH    1024
#define DD    135
#define NF    61        // rfft length = TS/2+1
#define GG    3072      // 3*H
#define NHEAD 4
#define DHD   256       // H / NHEAD

// padded K (bias column appended, rounded to 32)
#define KP1024 1056
#define KP135  160

#define NBLK_R 288      // persistent grid (2 CTAs/SM on 144 SMs)
#define NSLICE 6        // K-slices in recurrence

// smem stage layout (bf16 elements): AH | AL | WH | WL, each 128x40
#define SOFF_AL 5120
#define SOFF_WH 10240
#define SOFF_WL 15360
#define SST     20480                   // bf16 per stage
#define SMEM_BYTES (2 * SST * 2)        // 81920 B (2 stages)

typedef __nv_bfloat16 bf16;

// ---------------- weight split pools (bf16 hi/lo) ----------------------------
#define OFF_ATTNIN  0ull
#define OFF_WIH0    3244032ull
#define OFF_WHH0    3735552ull
#define OFF_WIH1    6979584ull
#define OFF_WHH1    10223616ull
#define OFF_FREQ    13467648ull
#define OFF_ATTNOUT 13631488ull
#define OFF_PRE     14712832ull
#define OFF_SPL1    15794176ull
#define WPOOL_TOTAL 17821696ull

__device__ bf16 g_whi[WPOOL_TOTAL];
__device__ bf16 g_wlo[WPOOL_TOTAL];

// ---------------- activation split pool (bf16 hi/lo) -------------------------
#define OFFA_IN    0ull          // (BT, 160)
#define OFFA_FRQ   4915200ull    // (BF, 160)
#define OFFA_FEAT  7413760ull    // (BF, 1056)
#define OFFA_SEQ   23904256ull   // (BT, 1056)
#define OFFA_OBAR  56344576ull   // (256, 1056)
#define OFFA_H0    56614912ull   // (256, 1056)
#define OFFA_H1    56885248ull   // (256, 1056)
#define OFFA_HID   57155584ull   // (256, 1056)
#define OFFA_XT    57425920ull   // (256, 160)
#define APOOL_TOTAL 57466880ull

__device__ bf16 g_ahi[APOOL_TOTAL];
__device__ bf16 g_alo[APOOL_TOTAL];

// ---------------- scratch buffers ---------------------------------------------
__device__ float g_big[(size_t)BB * TS * GG];         // gi / qkv / attn-out / diag
__device__ float g_seq[(size_t)BB * TS * HH];         // feat fp32
__device__ float g_in [(size_t)BB * TS * DD];
__device__ float g_frq[(size_t)BB * NF * DD];
__device__ float g_cosm[NF * TS];
__device__ float g_obar[BB * HH];
__device__ float g_mctx[BB * HH];
__device__ float g_h0[BB * HH];
__device__ float g_h1[BB * HH];
__device__ float g_ghp[(size_t)NSLICE * BB * GG];     // partials (gh)
__device__ float g_gxp[(size_t)NSLICE * BB * GG];     // partials (gx)
__device__ float g_prep[(size_t)8 * BB * HH];         // partials (pre)
__device__ float g_splp[(size_t)8 * BB * NJ * 128];   // partials (spl1)
__device__ float g_z1[BB * NJ * 128];
__device__ float g_p6[BB * NJ * 6];

// ---------------- software grid barrier ---------------------------------------
__device__ unsigned g_barcnt = 0;
__device__ unsigned g_barsense = 0;

__device__ __forceinline__ void grid_bar(unsigned nblk) {
    __syncthreads();
    if (threadIdx.x == 0) {
        unsigned my = *(volatile unsigned*)&g_barsense;
        __threadfence();
        unsigned arrived = atomicAdd(&g_barcnt, 1u);
        if (arrived == nblk - 1) {
            atomicExch(&g_barcnt, 0u);
            __threadfence();
            atomicExch(&g_barsense, my ^ 1u);
        } else {
            while (*(volatile unsigned*)&g_barsense == my) { }
            __threadfence();
        }
    }
    __syncthreads();
}

// ---------------- cp.async helpers ----------------------------------------------
__device__ __forceinline__ void cp16(bf16* dst, const bf16* src) {
    unsigned saddr = (unsigned)__cvta_generic_to_shared(dst);
    asm volatile("cp.async.cg.shared.global [%0], [%1], 16;\n" :: "r"(saddr), "l"(src));
}
#define CP_COMMIT() asm volatile("cp.async.commit_group;\n" ::: "memory")
#define CP_WAIT1()  asm volatile("cp.async.wait_group 1;\n" ::: "memory")
#define CP_WAIT0()  asm volatile("cp.async.wait_group 0;\n" ::: "memory")

__device__ __forceinline__ void stage_load(
    bf16* sb, const bf16* __restrict__ Ahi, const bf16* __restrict__ Alo,
    const bf16* __restrict__ Whi, const bf16* __restrict__ Wlo,
    int m0, int n0, int k0, int KP, int tid)
{
    #pragma unroll
    for (int it = 0; it < 2; it++) {
        int slot = tid + it * 256;       // 0..511
        int rw = slot >> 2;              // 0..127
        int col = (slot & 3) << 3;       // 0,8,16,24
        size_t aoff = (size_t)(m0 + rw) * KP + k0 + col;
        size_t woff = (size_t)(n0 + rw) * KP + k0 + col;
        int so = rw * 40 + col;
        cp16(sb + so,           Ahi + aoff);
        cp16(sb + SOFF_AL + so, Alo + aoff);
        cp16(sb + SOFF_WH + so, Whi + woff);
        cp16(sb + SOFF_WL + so, Wlo + woff);
    }
}

__device__ __forceinline__ void mma_stage(
    const bf16* sb, int wm, int wn,
    wmma::fragment<wmma::accumulator, 16, 16, 16, float> (&acc)[2][4])
{
    #pragma unroll
    for (int kk = 0; kk < 32; kk += 16) {
        wmma::fragment<wmma::matrix_a, 16, 16, 16, bf16, wmma::row_major> faH[2], faL[2];
        #pragma unroll
        for (int i = 0; i < 2; i++) {
            wmma::load_matrix_sync(faH[i], sb + (wm * 32 + i * 16) * 40 + kk, 40);
            wmma::load_matrix_sync(faL[i], sb + SOFF_AL + (wm * 32 + i * 16) * 40 + kk, 40);
        }
        #pragma unroll
        for (int j = 0; j < 4; j++) {
            wmma::fragment<wmma::matrix_b, 16, 16, 16, bf16, wmma::col_major> fbH, fbL;
            wmma::load_matrix_sync(fbH, sb + SOFF_WH + (wn * 64 + j * 16) * 40 + kk, 40);
            wmma::load_matrix_sync(fbL, sb + SOFF_WL + (wn * 64 + j * 16) * 40 + kk, 40);
            #pragma unroll
            for (int i = 0; i < 2; i++) {
                wmma::mma_sync(acc[i][j], faH[i], fbH, acc[i][j]);
                wmma::mma_sync(acc[i][j], faH[i], fbL, acc[i][j]);
                wmma::mma_sync(acc[i][j], faL[i], fbH, acc[i][j]);
            }
        }
    }
}

// ---------------- small utility kernels -------------------------------------

__global__ void copy_inseq_kernel(const float* __restrict__ poses, float* __restrict__ dst) {
    int idx = blockIdx.x * 256 + threadIdx.x;
    if (idx >= BB * TS * DD) return;
    int d = idx % DD;
    int t = (idx / DD) % TS;
    int b = idx / (TS * DD);
    dst[idx] = poses[((size_t)b * (TS + PREDN) + t) * DD + d];
}

__global__ void build_cos_kernel(float* __restrict__ cosm) {
    int idx = blockIdx.x * 256 + threadIdx.x;
    if (idx >= NF * TS) return;
    int f = idx / TS, t = idx % TS;
    cosm[idx] = (float)cos(2.0 * 3.14159265358979323846 * (double)(f * t) / (double)TS);
}

__global__ void freq_kernel(const float* __restrict__ inseq, const float* __restrict__ cosm,
                            float* __restrict__ freq) {
    int b = blockIdx.x, f = blockIdx.y, d = threadIdx.x;
    if (d >= DD) return;
    const float* xp = inseq + (size_t)b * TS * DD + d;
    const float* cp = cosm + f * TS;
    float s = 0.f;
    #pragma unroll 4
    for (int t = 0; t < TS; t++) s += cp[t] * xp[(size_t)t * DD];
    freq[((size_t)b * NF + f) * DD + d] = s;
}

// ---------------- weight/activation splitters ---------------------------------
__global__ void split_w_kernel(const float* __restrict__ W, const float* __restrict__ bias,
                               bf16* __restrict__ hi, bf16* __restrict__ lo,
                               int N, int K, int KP) {
    size_t idx = (size_t)blockIdx.x * 256 + threadIdx.x;
    if (idx >= (size_t)N * KP) return;
    int k = (int)(idx % KP);
    int n = (int)(idx / KP);
    float v = 0.f;
    if (k < K) v = W[(size_t)n * K + k];
    else if (k == K) v = bias[n];
    bf16 h = __float2bfloat16(v);
    hi[idx] = h;
    lo[idx] = __float2bfloat16(v - __bfloat162float(h));
}

__global__ void split_a_kernel(const float* __restrict__ A,
                               bf16* __restrict__ hi, bf16* __restrict__ lo,
                               int M, int K, int KP) {
    size_t idx = (size_t)blockIdx.x * 256 + threadIdx.x;
    if (idx >= (size_t)M * KP) return;
    int k = (int)(idx % KP);
    int m = (int)(idx / KP);
    float v = 0.f;
    if (k < K) v = A[(size_t)m * K + k];
    else if (k == K) v = 1.0f;
    bf16 h = __float2bfloat16(v);
    hi[idx] = h;
    lo[idx] = __float2bfloat16(v - __bfloat162float(h));
}

__global__ void zero_split_kernel(bf16* __restrict__ hi, bf16* __restrict__ lo,
                                  int M, int K, int KP) {
    size_t idx = (size_t)blockIdx.x * 256 + threadIdx.x;
    if (idx >= (size_t)M * KP) return;
    int k = (int)(idx % KP);
    float v = (k == K) ? 1.0f : 0.0f;
    hi[idx] = __float2bfloat16(v);
    lo[idx] = __float2bfloat16(0.0f);
}

// ---------------- double-buffered pre-split bf16 GEMM --------------------------
__global__ __launch_bounds__(256, 2) void gemm4_kernel(
    const bf16* __restrict__ Ahi, const bf16* __restrict__ Alo,
    const bf16* __restrict__ Whi, const bf16* __restrict__ Wlo,
    float* __restrict__ C, int M, int N, int KP)
{
    extern __shared__ __align__(16) bf16 sm4[];
    int tid = threadIdx.x;
    int warp = tid >> 5;
    int wm = warp >> 1, wn = warp & 1;
    int m0 = blockIdx.y * 128, n0 = blockIdx.x * 128;

    wmma::fragment<wmma::accumulator, 16, 16, 16, float> acc[2][4];
    #pragma unroll
    for (int i = 0; i < 2; i++)
        #pragma unroll
        for (int j = 0; j < 4; j++)
            wmma::fill_fragment(acc[i][j], 0.0f);

    int CH  = KP >> 5;
    int cpz = (CH + gridDim.z - 1) / gridDim.z;
    int c0  = blockIdx.z * cpz;
    int c1  = c0 + cpz; if (c1 > CH) c1 = CH;
    int nch = c1 - c0;

    if (nch > 0) {
        stage_load(sm4, Ahi, Alo, Whi, Wlo, m0, n0, c0 << 5, KP, tid);
        CP_COMMIT();
    }
    for (int i = 0; i < nch; i++) {
        bf16* sb = sm4 + (i & 1) * SST;
        if (i + 1 < nch) {
            stage_load(sm4 + ((i + 1) & 1) * SST, Ahi, Alo, Whi, Wlo,
                       m0, n0, (c0 + i + 1) << 5, KP, tid);
            CP_COMMIT();
            CP_WAIT1();
        } else {
            CP_WAIT0();
        }
        __syncthreads();
        mma_stage(sb, wm, wn, acc);
        __syncthreads();
    }

    float* Cz = C + (size_t)blockIdx.z * M * N;
    #pragma unroll
    for (int i = 0; i < 2; i++)
        #pragma unroll
        for (int j = 0; j < 4; j++)
            wmma::store_matrix_sync(
                Cz + (size_t)(m0 + wm * 32 + i * 16) * N + (n0 + wn * 64 + j * 16),
                acc[i][j], N, wmma::mem_row_major);
}

// ---------------- persistent GRU recurrence (288 CTAs, 2/SM) ------------------
__global__ __launch_bounds__(256, 2) void gru_persist_kernel(
    const float* __restrict__ gi,          // (B, TS, GG), bih fused
    const bf16* __restrict__ Whi,          // (GG, KP1024), bhh in col HH
    const bf16* __restrict__ Wlo,
    float* __restrict__ h,                 // (B, HH) fp32, pre-zeroed
    bf16* __restrict__ hhi,                // (B, KP1024), pre-inited
    bf16* __restrict__ hlo,
    float* __restrict__ ghp,               // (NSLICE, B, GG) partials
    bf16* __restrict__ seqhi,              // (B, TS, KP1024) or null
    bf16* __restrict__ seqlo,
    int nsteps)
{
    extern __shared__ __align__(16) bf16 sm4[];
    int tid = threadIdx.x;
    int warp = tid >> 5;
    int wm = warp >> 1, wn = warp & 1;
    int tile  = blockIdx.x % 48;
    int slice = blockIdx.x / 48;           // 0..5
    int m0 = (tile / 24) * 128;
    int n0 = (tile % 24) * 128;
    const int CH = KP1024 >> 5;            // 33
    int c0 = slice * 6;
    int c1 = c0 + 6; if (c1 > CH) c1 = CH;
    int nch = c1 - c0;                     // 6 (slice 5: 3)

    for (int t = 0; t < nsteps; t++) {
        // ---- phase 1: partial gh = h @ Whh^T over this k-slice ----
        wmma::fragment<wmma::accumulator, 16, 16, 16, float> acc[2][4];
        #pragma unroll
        for (int i = 0; i < 2; i++)
            #pragma unroll
            for (int j = 0; j < 4; j++)
                wmma::fill_fragment(acc[i][j], 0.0f);

        stage_load(sm4, hhi, hlo, Whi, Wlo, m0, n0, c0 << 5, KP1024, tid);
        CP_COMMIT();
        for (int i = 0; i < nch; i++) {
            bf16* sb = sm4 + (i & 1) * SST;
            if (i + 1 < nch) {
                stage_load(sm4 + ((i + 1) & 1) * SST, hhi, hlo, Whi, Wlo,
                           m0, n0, (c0 + i + 1) << 5, KP1024, tid);
                CP_COMMIT();
                CP_WAIT1();
            } else {
                CP_WAIT0();
            }
            __syncthreads();
            mma_stage(sb, wm, wn, acc);
            __syncthreads();
        }

        float* Cz = ghp + (size_t)slice * (BB * GG);
        #pragma unroll
        for (int i = 0; i < 2; i++)
            #pragma unroll
            for (int j = 0; j < 4; j++)
                wmma::store_matrix_sync(
                    Cz + (size_t)(m0 + wm * 32 + i * 16) * GG + (n0 + wn * 64 + j * 16),
                    acc[i][j], GG, wmma::mem_row_major);

        __threadfence();
        grid_bar(NBLK_R);

        // ---- phase 2: gate math ----
        for (int idx = blockIdx.x * 256 + tid; idx < BB * HH; idx += NBLK_R * 256) {
            int b = idx >> 10, j = idx & 1023;
            const float* gib = gi + ((size_t)b * TS + t) * GG;
            float ir = gib[j], iz = gib[HH + j], inn = gib[2 * HH + j];
            float hr = 0.f, hz = 0.f, hn = 0.f;
            #pragma unroll
            for (int s = 0; s < NSLICE; s++) {
                const float* g = ghp + (size_t)s * (BB * GG) + (size_t)b * GG;
                hr += __ldcg(&g[j]);
                hz += __ldcg(&g[HH + j]);
                hn += __ldcg(&g[2 * HH + j]);
            }
            float r = 1.f / (1.f + expf(-(ir + hr)));
            float z = 1.f / (1.f + expf(-(iz + hz)));
            float n = tanhf(inn + r * hn);
            float hp = __ldcg(&h[idx]);
            float hnew = (1.f - z) * n + z * hp;
            h[idx] = hnew;
            bf16 hb = __float2bfloat16(hnew);
            bf16 lb = __float2bfloat16(hnew - __bfloat162float(hb));
            size_t ho = (size_t)b * KP1024 + j;
            hhi[ho] = hb;
            hlo[ho] = lb;
            if (seqhi) {
                size_t so = ((size_t)b * TS + t) * KP1024 + j;
                seqhi[so] = hb;
                seqlo[so] = lb;
            }
        }
        __threadfence();
        grid_bar(NBLK_R);
    }
}

// ---------------- attention ---------------------------------------------------
__global__ __launch_bounds__(256) void attention_kernel(const float* __restrict__ qkv,
                                                        float* __restrict__ o) {
    extern __shared__ float sm[];
    float* kv = sm;
    float* sc = sm + NF * DHD;
    int b = blockIdx.x >> 2;
    int h = blockIdx.x & 3;
    int tid = threadIdx.x;
    int lane = tid & 31, w = tid >> 5;
    const float* base = qkv + (size_t)b * NF * GG + h * DHD;

    for (int idx = tid; idx < NF * DHD; idx += 256) {
        int t = idx >> 8, d = idx & 255;
        kv[idx] = base[(size_t)t * GG + HH + d];
    }
    __syncthreads();
    for (int i = w; i < NF; i += 8) {
        float q[8];
        const float* qp = base + (size_t)i * GG;
        #pragma unroll
        for (int c = 0; c < 8; c++) q[c] = qp[lane + 32 * c];
        for (int j = 0; j < NF; j++) {
            const float* kp = kv + j * DHD;
            float s = 0.f;
            #pragma unroll
            for (int c = 0; c < 8; c++) s += q[c] * kp[lane + 32 * c];
            #pragma unroll
            for (int off = 16; off; off >>= 1) s += __shfl_xor_sync(0xffffffffu, s, off);
            if (lane == 0) sc[i * 64 + j] = s * 0.0625f;
        }
    }
    __syncthreads();
    for (int i = w; i < NF; i += 8) {
        float v0 = (lane < NF) ? sc[i * 64 + lane] : -1e30f;
        float v1 = (lane + 32 < NF) ? sc[i * 64 + lane + 32] : -1e30f;
        float m = fmaxf(v0, v1);
        #pragma unroll
        for (int off = 16; off; off >>= 1) m = fmaxf(m, __shfl_xor_sync(0xffffffffu, m, off));
        float e0 = (lane < NF) ? expf(v0 - m) : 0.f;
        float e1 = (lane + 32 < NF) ? expf(v1 - m) : 0.f;
        float ss = e0 + e1;
        #pragma unroll
        for (int off = 16; off; off >>= 1) ss += __shfl_xor_sync(0xffffffffu, ss, off);
        float inv = 1.f / ss;
        if (lane < NF) sc[i * 64 + lane] = e0 * inv;
        if (lane + 32 < NF) sc[i * 64 + lane + 32] = e1 * inv;
    }
    __syncthreads();
    for (int idx = tid; idx < NF * DHD; idx += 256) {
        int t = idx >> 8, d = idx & 255;
        kv[idx] = base[(size_t)t * GG + 2 * HH + d];
    }
    __syncthreads();
    float acc[NF];
    #pragma unroll
    for (int i = 0; i < NF; i++) acc[i] = 0.f;
    int d = tid;
    for (int j = 0; j < NF; j++) {
        float vv = kv[j * DHD + d];
        #pragma unroll
        for (int i = 0; i < NF; i++) acc[i] += sc[i * 64 + j] * vv;
    }
    float* ob = o + (size_t)b * NF * HH + h * DHD + d;
    #pragma unroll
    for (int i = 0; i < NF; i++) ob[(size_t)i * HH] = acc[i];
}

__global__ void mean61_kernel(const float* __restrict__ o, float* __restrict__ obar) {
    int idx = blockIdx.x * 256 + threadIdx.x;
    if (idx >= BB * HH) return;
    int b = idx >> 10, c = idx & 1023;
    const float* p = o + (size_t)b * NF * HH + c;
    float s = 0.f;
    for (int t = 0; t < NF; t++) s += p[(size_t)t * HH];
    obar[idx] = s * (1.f / (float)NF);
}

// ---------------- GRU gate math (decode) ---------------------------------------
__global__ void gru_gate2(const float* __restrict__ gxp, int gx_sk,
                          const float* __restrict__ ghp, int gh_sk,
                          float* __restrict__ h,
                          bf16* __restrict__ hhi, bf16* __restrict__ hlo) {
    int idx = blockIdx.x * 256 + threadIdx.x;
    if (idx >= BB * HH) return;
    int b = idx >> 10, j = idx & 1023;
    float ir = 0.f, iz = 0.f, in = 0.f;
    for (int s = 0; s < gx_sk; s++) {
        const float* g = gxp + (size_t)s * (BB * GG) + (size_t)b * GG;
        ir += g[j]; iz += g[HH + j]; in += g[2 * HH + j];
    }
    float hr = 0.f, hz = 0.f, hn = 0.f;
    for (int s = 0; s < gh_sk; s++) {
        const float* g = ghp + (size_t)s * (BB * GG) + (size_t)b * GG;
        hr += g[j]; hz += g[HH + j]; hn += g[2 * HH + j];
    }
    float r = 1.f / (1.f + expf(-(ir + hr)));
    float z = 1.f / (1.f + expf(-(iz + hz)));
    float n = tanhf(in + r * hn);
    float hp = h[idx];
    float hnew = (1.f - z) * n + z * hp;
    h[idx] = hnew;
    bf16 hb = __float2bfloat16(hnew);
    size_t ho = (size_t)b * KP1024 + j;
    hhi[ho] = hb;
    hlo[ho] = __float2bfloat16(hnew - __bfloat162float(hb));
}

// ---------------- split-K reductions --------------------------------------------
__global__ void reduce_act_kernel(const float* __restrict__ part, int sk, int mn,
                                  float* __restrict__ out) {
    int idx = blockIdx.x * 256 + threadIdx.x;
    if (idx >= mn) return;
    float s = 0.f;
    for (int i = 0; i < sk; i++) s += part[(size_t)i * mn + idx];
    out[idx] = fmaxf(s, 0.f);
}

__global__ void reduce_split_kernel(const float* __restrict__ part, int sk,
                                    const float* __restrict__ addend,
                                    bf16* __restrict__ hi, bf16* __restrict__ lo) {
    int idx = blockIdx.x * 256 + threadIdx.x;
    if (idx >= BB * HH) return;
    int b = idx >> 10, j = idx & 1023;
    float s = 0.f;
    for (int i = 0; i < sk; i++) s += part[(size_t)i * (BB * HH) + idx];
    s = fmaxf(s, 0.f) + addend[idx];
    bf16 hb = __float2bfloat16(s);
    size_t o = (size_t)b * KP1024 + j;
    hi[o] = hb;
    lo[o] = __float2bfloat16(s - __bfloat162float(hb));
}

// ---------------- decode init ---------------------------------------------------
__global__ void init_decode(const float* __restrict__ inseq,
                            bf16* __restrict__ xthi, bf16* __restrict__ xtlo,
                            float* __restrict__ p6) {
    int idx = blockIdx.x * 256 + threadIdx.x;
    if (idx >= BB * KP135) return;
    int b = idx / KP135, d = idx % KP135;
    const float* last = inseq + ((size_t)b * TS + (TS - 1)) * DD;
    float v = 0.f;
    if (d < DD) v = last[d];
    else if (d == DD) v = 1.0f;
    bf16 hb = __float2bfloat16(v);
    xthi[idx] = hb;
    xtlo[idx] = __float2bfloat16(v - __bfloat162float(hb));
    if (d < NJ * 6) {
        int j = d / 6, o = d % 6;
        int src = (o < 3) ? (j * 9 + o * 3) : (j * 9 + (o - 3) * 3 + 1);
        p6[(size_t)b * 90 + d] = last[src];
    }
}

// ---------------- spl head layer2 + rot6d (writes split xt) ---------------------
__global__ __launch_bounds__(192) void spl2_rot(const float* __restrict__ z1,
                                                const float* __restrict__ w2,
                                                const float* __restrict__ b2,
                                                float* __restrict__ p6,
                                                bf16* __restrict__ xthi,
                                                bf16* __restrict__ xtlo,
                                                float* __restrict__ out, int step) {
    int bj = blockIdx.x;
    int b = bj / NJ, j = bj % NJ;
    int w = threadIdx.x >> 5, lane = threadIdx.x & 31;
    __shared__ float v6[6];
    const float* zz = z1 + (size_t)b * (NJ * 128) + j * 128;
    const float* ww = w2 + ((size_t)j * 6 + w) * 128;
    float s = 0.f;
    #pragma unroll
    for (int c = 0; c < 4; c++) s += zz[lane + 32 * c] * ww[lane + 32 * c];
    #pragma unroll
    for (int off = 16; off; off >>= 1) s += __shfl_xor_sync(0xffffffffu, s, off);
    if (lane == 0)
        v6[w] = p6[(size_t)b * 90 + j * 6 + w] + s + b2[j * 6 + w];
    __syncthreads();
    if (threadIdx.x < 6) {
        float v = v6[threadIdx.x];
        p6[(size_t)b * 90 + j * 6 + threadIdx.x] = v;
        out[((size_t)b * PREDN + step) * 90 + j * 6 + threadIdx.x] = v;
    }
    if (threadIdx.x == 0) {
        float a1x = v6[0], a2x = v6[1], a1y = v6[2], a2y = v6[3], a1z = v6[4], a2z = v6[5];
        float n1 = fmaxf(sqrtf(a1x*a1x + a1y*a1y + a1z*a1z), 1e-12f);
        float b1x = a1x / n1, b1y = a1y / n1, b1z = a1z / n1;
        float dot = b1x*a2x + b1y*a2y + b1z*a2z;
        float ox = a2x - dot*b1x, oy = a2y - dot*b1y, oz = a2z - dot*b1z;
        float n2 = fmaxf(sqrtf(ox*ox + oy*oy + oz*oz), 1e-12f);
        float b2x = ox / n2, b2y = oy / n2, b2z = oz / n2;
        float b3x = b1y*b2z - b1z*b2y;
        float b3y = b1z*b2x - b1x*b2z;
        float b3z = b1x*b2y - b1y*b2x;
        float rm[9] = { b1x, b2x, b3x, b1y, b2y, b3y, b1z, b2z, b3z };
        size_t base = (size_t)b * KP135 + j * 9;
        #pragma unroll
        for (int c = 0; c < 9; c++) {
            bf16 hb = __float2bfloat16(rm[c]);
            xthi[base + c] = hb;
            xtlo[base + c] = __float2bfloat16(rm[c] - __bfloat162float(hb));
        }
    }
}

// ---------------- host orchestration ---------------------------------------------

static inline void gemm4(const bf16* ahi, const bf16* alo,
                         const bf16* whi, const bf16* wlo,
                         float* C, int M, int N, int KP, int sk) {
    dim3 g(N / 128, M / 128, sk);
    gemm4_kernel<<<g, 256, SMEM_BYTES>>>(ahi, alo, whi, wlo, C, M, N, KP);
}

static inline void splitw(const float* W, const float* bias,
                          bf16* hi, bf16* lo, int N, int K, int KP) {
    size_t n = (size_t)N * KP;
    split_w_kernel<<<(int)((n + 255) / 256), 256>>>(W, bias, hi, lo, N, K, KP);
}

static inline void splita(const float* A, bf16* hi, bf16* lo, int M, int K, int KP) {
    size_t n = (size_t)M * KP;
    split_a_kernel<<<(int)((n + 255) / 256), 256>>>(A, hi, lo, M, K, KP);
}

static inline void zerosplit(bf16* hi, bf16* lo, int M, int K, int KP) {
    size_t n = (size_t)M * KP;
    zero_split_kernel<<<(int)((n + 255) / 256), 256>>>(hi, lo, M, K, KP);
}

extern "C" void kernel_launch(void* const* d_in, const int* in_sizes, int n_in,
                              void* d_out, int out_size) {
    const float* poses      = (const float*)d_in[0];
    const float* freq_w     = (const float*)d_in[1];
    const float* freq_b     = (const float*)d_in[2];
    const float* attn_in_w  = (const float*)d_in[3];
    const float* attn_in_b  = (const float*)d_in[4];
    const float* attn_out_w = (const float*)d_in[5];
    const float* attn_out_b = (const float*)d_in[6];
    const float* gru_wih0   = (const float*)d_in[7];
    const float* gru_whh0   = (const float*)d_in[8];
    const float* gru_bih0   = (const float*)d_in[9];
    const float* gru_bhh0   = (const float*)d_in[10];
    const float* gru_wih1   = (const float*)d_in[11];
    const float* gru_whh1   = (const float*)d_in[12];
    const float* gru_bih1   = (const float*)d_in[13];
    const float* gru_bhh1   = (const float*)d_in[14];
    const float* pre_w      = (const float*)d_in[15];
    const float* pre_b      = (const float*)d_in[16];
    const float* spl_w1     = (const float*)d_in[17];
    const float* spl_b1     = (const float*)d_in[18];
    const float* spl_w2     = (const float*)d_in[19];
    const float* spl_b2     = (const float*)d_in[20];
    float* out = (float*)d_out;

    float *pBig, *pSeq, *pIn, *pFrq, *pCos, *pObar, *pMctx, *pH0, *pH1,
          *pGhp, *pGxp, *pPrep, *pSplp, *pZ1, *pP6;
    bf16 *pWhi, *pWlo, *pAhi, *pAlo;
    cudaGetSymbolAddress((void**)&pBig, g_big);
    cudaGetSymbolAddress((void**)&pSeq, g_seq);
    cudaGetSymbolAddress((void**)&pIn,  g_in);
    cudaGetSymbolAddress((void**)&pFrq, g_frq);
    cudaGetSymbolAddress((void**)&pCos, g_cosm);
    cudaGetSymbolAddress((void**)&pObar, g_obar);
    cudaGetSymbolAddress((void**)&pMctx, g_mctx);
    cudaGetSymbolAddress((void**)&pH0, g_h0);
    cudaGetSymbolAddress((void**)&pH1, g_h1);
    cudaGetSymbolAddress((void**)&pGhp, g_ghp);
    cudaGetSymbolAddress((void**)&pGxp, g_gxp);
    cudaGetSymbolAddress((void**)&pPrep, g_prep);
    cudaGetSymbolAddress((void**)&pSplp, g_splp);
    cudaGetSymbolAddress((void**)&pZ1, g_z1);
    cudaGetSymbolAddress((void**)&pP6, g_p6);
    cudaGetSymbolAddress((void**)&pWhi, g_whi);
    cudaGetSymbolAddress((void**)&pWlo, g_wlo);
    cudaGetSymbolAddress((void**)&pAhi, g_ahi);
    cudaGetSymbolAddress((void**)&pAlo, g_alo);

    cudaFuncSetAttribute(gemm4_kernel, cudaFuncAttributeMaxDynamicSharedMemorySize, SMEM_BYTES);
    cudaFuncSetAttribute(gru_persist_kernel, cudaFuncAttributeMaxDynamicSharedMemorySize, SMEM_BYTES);

    float* qkv   = pBig;
    float* attno = pBig + (size_t)BB * NF * GG;
    float* gi    = pBig;
    float* feat  = pSeq;

    const int BF = BB * NF;   // 15616
    const int BT = BB * TS;   // 30720

    // ---- launches 1-5, then DIAG gemm4 as launch #6 (ncu -s 5 -c 1 target) ----
    copy_inseq_kernel<<<(BB*TS*DD + 255) / 256, 256>>>(poses, pIn);          // 1
    build_cos_kernel<<<(NF*TS + 255) / 256, 256>>>(pCos);                    // 2
    freq_kernel<<<dim3(BB, NF), 160>>>(pIn, pCos, pFrq);                     // 3
    splitw(attn_in_w, attn_in_b, pWhi + OFF_ATTNIN, pWlo + OFF_ATTNIN,
           GG, HH, KP1024);                                                  // 4
    splitw(freq_w, freq_b, pWhi + OFF_FREQ, pWlo + OFF_FREQ, HH, DD, KP135); // 5
    // DIAG: representative big-K gemm4 on already-split weight data (#6).
    // Output region is dead scratch (g_big is rewritten by qkv/gi later).
    gemm4(pWhi + OFF_ATTNIN, pWlo + OFF_ATTNIN,
          pWhi + OFF_ATTNIN, pWlo + OFF_ATTNIN, pBig, 1536, GG, KP1024, 1);  // 6

    // ---- remaining one-time weight splits ----
    splitw(gru_wih0,  gru_bih0,  pWhi + OFF_WIH0,    pWlo + OFF_WIH0,    GG, DD, KP135);
    splitw(gru_whh0,  gru_bhh0,  pWhi + OFF_WHH0,    pWlo + OFF_WHH0,    GG, HH, KP1024);
    splitw(gru_wih1,  gru_bih1,  pWhi + OFF_WIH1,    pWlo + OFF_WIH1,    GG, HH, KP1024);
    splitw(gru_whh1,  gru_bhh1,  pWhi + OFF_WHH1,    pWlo + OFF_WHH1,    GG, HH, KP1024);
    splitw(attn_out_w,attn_out_b,pWhi + OFF_ATTNOUT, pWlo + OFF_ATTNOUT, HH, HH, KP1024);
    splitw(pre_w,     pre_b,     pWhi + OFF_PRE,     pWlo + OFF_PRE,     HH, HH, KP1024);
    splitw(spl_w1,    spl_b1,    pWhi + OFF_SPL1,    pWlo + OFF_SPL1,    NJ*128, HH, KP1024);

    // ---- activation split buffer init (ones/zero pad cols) ----
    zerosplit(pAhi + OFFA_SEQ, pAlo + OFFA_SEQ, BT, HH, KP1024);
    zerosplit(pAhi + OFFA_H0,  pAlo + OFFA_H0,  BB, HH, KP1024);
    zerosplit(pAhi + OFFA_H1,  pAlo + OFFA_H1,  BB, HH, KP1024);
    zerosplit(pAhi + OFFA_HID, pAlo + OFFA_HID, BB, HH, KP1024);

    // ---- frequency attention branch ----
    splita(pFrq, pAhi + OFFA_FRQ, pAlo + OFFA_FRQ, BF, DD, KP135);
    gemm4(pAhi + OFFA_FRQ, pAlo + OFFA_FRQ, pWhi + OFF_FREQ, pWlo + OFF_FREQ,
          feat, BF, HH, KP135, 1);
    splita(feat, pAhi + OFFA_FEAT, pAlo + OFFA_FEAT, BF, HH, KP1024);
    gemm4(pAhi + OFFA_FEAT, pAlo + OFFA_FEAT, pWhi + OFF_ATTNIN, pWlo + OFF_ATTNIN,
          qkv, BF, GG, KP1024, 1);

    int smem_attn = (NF * DHD + NF * 64) * (int)sizeof(float);
    cudaFuncSetAttribute(attention_kernel, cudaFuncAttributeMaxDynamicSharedMemorySize, smem_attn);
    attention_kernel<<<BB * NHEAD, 256, smem_attn>>>(qkv, attno);
    mean61_kernel<<<(BB*HH + 255) / 256, 256>>>(attno, pObar);
    splita(pObar, pAhi + OFFA_OBAR, pAlo + OFFA_OBAR, BB, HH, KP1024);
    gemm4(pAhi + OFFA_OBAR, pAlo + OFFA_OBAR, pWhi + OFF_ATTNOUT, pWlo + OFF_ATTNOUT,
          pMctx, BB, HH, KP1024, 1);

    // ---- GRU layer 0 (persistent recurrence, 288 CTAs) ----
    splita(pIn, pAhi + OFFA_IN, pAlo + OFFA_IN, BT, DD, KP135);
    gemm4(pAhi + OFFA_IN, pAlo + OFFA_IN, pWhi + OFF_WIH0, pWlo + OFF_WIH0,
          gi, BT, GG, KP135, 1);
    cudaMemsetAsync(pH0, 0, (size_t)BB * HH * sizeof(float));
    gru_persist_kernel<<<NBLK_R, 256, SMEM_BYTES>>>(gi, pWhi + OFF_WHH0, pWlo + OFF_WHH0,
                                      pH0, pAhi + OFFA_H0, pAlo + OFFA_H0, pGhp,
                                      pAhi + OFFA_SEQ, pAlo + OFFA_SEQ, TS);

    // ---- GRU layer 1 (persistent recurrence) ----
    gemm4(pAhi + OFFA_SEQ, pAlo + OFFA_SEQ, pWhi + OFF_WIH1, pWlo + OFF_WIH1,
          gi, BT, GG, KP1024, 1);
    cudaMemsetAsync(pH1, 0, (size_t)BB * HH * sizeof(float));
    gru_persist_kernel<<<NBLK_R, 256, SMEM_BYTES>>>(gi, pWhi + OFF_WHH1, pWlo + OFF_WHH1,
                                      pH1, pAhi + OFFA_H1, pAlo + OFFA_H1, pGhp,
                                      nullptr, nullptr, TS);

    // ---- autoregressive decode ----
    init_decode<<<(BB*KP135 + 255) / 256, 256>>>(pIn, pAhi + OFFA_XT, pAlo + OFFA_XT, pP6);
    for (int s = 0; s < PREDN; s++) {
        gemm4(pAhi + OFFA_XT, pAlo + OFFA_XT, pWhi + OFF_WIH0, pWlo + OFF_WIH0,
              pGxp, BB, GG, KP135, 2);
        gemm4(pAhi + OFFA_H0, pAlo + OFFA_H0, pWhi + OFF_WHH0, pWlo + OFF_WHH0,
              pGhp, BB, GG, KP1024, 6);
        gru_gate2<<<(BB*HH)/256, 256>>>(pGxp, 2, pGhp, 6, pH0,
                                        pAhi + OFFA_H0, pAlo + OFFA_H0);

        gemm4(pAhi + OFFA_H0, pAlo + OFFA_H0, pWhi + OFF_WIH1, pWlo + OFF_WIH1,
              pGxp, BB, GG, KP1024, 6);
        gemm4(pAhi + OFFA_H1, pAlo + OFFA_H1, pWhi + OFF_WHH1, pWlo + OFF_WHH1,
              pGhp, BB, GG, KP1024, 6);
        gru_gate2<<<(BB*HH)/256, 256>>>(pGxp, 6, pGhp, 6, pH1,
                                        pAhi + OFFA_H1, pAlo + OFFA_H1);

        gemm4(pAhi + OFFA_H1, pAlo + OFFA_H1, pWhi + OFF_PRE, pWlo + OFF_PRE,
              pPrep, BB, HH, KP1024, 8);
        reduce_split_kernel<<<(BB*HH + 255)/256, 256>>>(pPrep, 8, pMctx,
                                                        pAhi + OFFA_HID, pAlo + OFFA_HID);

        gemm4(pAhi + OFFA_HID, pAlo + OFFA_HID, pWhi + OFF_SPL1, pWlo + OFF_SPL1,
              pSplp, BB, NJ*128, KP1024, 8);
        reduce_act_kernel<<<(BB*NJ*128 + 255)/256, 256>>>(pSplp, 8, BB*NJ*128, pZ1);

        spl2_rot<<<BB * NJ, 192>>>(pZ1, spl_w2, spl_b2, pP6,
                                   pAhi + OFFA_XT, pAlo + OFFA_XT, out, s);
    }
}